// round 13
// baseline (speedup 1.0000x reference)
#include <cuda_runtime.h>
#include <stdint.h>

// HierarchicalRingTopK: 3x3x3 VALID conv (120 ch) + 4-level gated top-k keep.
// x: (8,3,256,256) f32, w: (120,3,3,3) f32, b: (120,) f32 -> out: (8,120,254,254) f32
//
// FROZEN NUMERICS (rel_err == 0.0 since R4): per-channel serial fp32 FMA chain
// over 27 taps in Eigen/NHWC order (kh, kw, ci innermost) from 0, bias added
// as a separate fp32 add. Keys rotl(bits,1). Top-k: magnitude strict-> scan,
// lower index wins ties. f32x2 lanes are independent rn-FMAs (bit-identical).
//
// R12: two ADJACENT pixels (h,w),(h,w+1) per thread. Overlapping windows ->
// only 36 unique taps (72 regs) so 2px fits 128 regs / 4 CTAs / 16 warps.
// One weight LDS.128 stream feeds both pixels -> weight wavefronts halve.
// sEnc time-shared: levels 0-2 A@cols0-31 B@cols32-63; level 3 popc-compacted
// (<=32 live/pixel). Weights staged in Eigen tap order so JIT ulonglong2
// loads preserve the frozen chain. Zero-prefill via float2 covers both px.

#define BT 128
#define OH 254
#define OW 254
#define PLANE (OH * OW)            // 64516
#define NPIX (8 * PLANE)           // 516128
#define NPAIRS_PIX (NPIX / 2)      // 258064
#define NCH 120
#define NPAIR (NCH / 2)            // 60

__device__ __forceinline__ unsigned long long ffma2(unsigned long long a,
                                                    unsigned long long bb_,
                                                    unsigned long long c) {
    unsigned long long d;
    asm("fma.rn.f32x2 %0, %1, %2, %3;" : "=l"(d) : "l"(a), "l"(bb_), "l"(c));
    return d;
}
__device__ __forceinline__ unsigned long long pack2(float lo, float hi) {
    unsigned long long r;
    asm("mov.b64 %0, {%1, %2};" : "=l"(r) : "f"(lo), "f"(hi));
    return r;
}
__device__ __forceinline__ void unpack2(unsigned long long v, float& lo, float& hi) {
    asm("mov.b64 {%0, %1}, %2;" : "=f"(lo), "=f"(hi) : "l"(v));
}

// Gating: selected j -> enable bits 2j..2j+3 (mod 2n). Branch-free bit-spread.
// Validated rel_err==0.0 in R8-R11. Handles the j==31 wrap for n=32.
__device__ __forceinline__ unsigned long long gate_from_sel(unsigned m, int n) {
    unsigned long long xv = m;
    xv = (xv | (xv << 16)) & 0x0000FFFF0000FFFFull;
    xv = (xv | (xv << 8 )) & 0x00FF00FF00FF00FFull;
    xv = (xv | (xv << 4 )) & 0x0F0F0F0F0F0F0F0Full;
    xv = (xv | (xv << 2 )) & 0x3333333333333333ull;
    xv = (xv | (xv << 1 )) & 0x5555555555555555ull;     // bit j -> bit 2j
    unsigned long long gg = xv | (xv << 1) | (xv << 2) | (xv << 3);
    if (n == 32 && (m >> 31)) gg |= 0x3ull;             // wrap of j=31
    const int Wn = n * 2;
    if (Wn < 64)
        gg = (gg | (gg >> Wn)) & ((1ull << Wn) - 1ull);
    return gg;
}

// Index of the n-th (0-based) set bit of v. Caller guarantees popcll(v) > n.
__device__ __forceinline__ int nth_set_bit(unsigned long long v, int n) {
    unsigned part = (unsigned)v;
    int idx = 0, c = __popc(part);
    if (n >= c) { part = (unsigned)(v >> 32); idx = 32; n -= c; }
    c = __popc(part & 0xFFFFu); if (n >= c) { idx += 16; part >>= 16; n -= c; }
    c = __popc(part & 0xFFu);   if (n >= c) { idx += 8;  part >>= 8;  n -= c; }
    c = __popc(part & 0xFu);    if (n >= c) { idx += 4;  part >>= 4;  n -= c; }
    c = __popc(part & 0x3u);    if (n >= c) { idx += 2;  part >>= 2;  n -= c; }
    c = part & 0x1u;            if (n >= c) { idx += 1; }
    return idx;
}

__global__ void __launch_bounds__(BT, 4)
hrtk_kernel(const float* __restrict__ x,
            const float* __restrict__ w,
            const float* __restrict__ b,
            float* __restrict__ out)
{
    // Eigen-tap-order pair-interleaved weights:
    // wshE[pr*56 + 2*ei + e] = w[2pr+e][tap(ei)], ei = kh*9+kw*3+ci (Eigen order);
    // slots 54/55 = biases. One ulonglong2 load = taps ei=2z,2z+1 for (ch0,ch1).
    __shared__ float    wshE[NPAIR * 56];    // 13440 B
    __shared__ unsigned sEnc[64 * BT];       // 32768 B (A: cols 0-31, B: 32-63)

    const int t = threadIdx.x;

    for (int s = t; s < NPAIR * 56; s += BT) {
        const int pr = s / 56;
        const int r  = s - pr * 56;
        float v;
        if (r < 54) {
            const int ei = r >> 1, e = r & 1;
            const int kh = ei / 9, kw = (ei % 9) / 3, ci = ei % 3;
            const int qm = ci * 9 + kh * 3 + kw;     // OIHW memory tap index
            v = w[(pr * 2 + e) * 27 + qm];
        } else {
            v = b[pr * 2 + (r - 54)];
        }
        wshE[s] = v;
    }
    __syncthreads();

    // Pair q -> pixels 2q (A) and 2q+1 (B); OW even => always same row, wA even.
    int q = blockIdx.x * BT + t;
    if (q >= NPAIRS_PIX) q = NPAIRS_PIX - 1;   // clamp: duplicates write identical values
    const int pA = 2 * q;
    const int wA = pA % OW;
    const int rest = pA / OW;
    const int hh = rest % OH;
    const int bb = rest / OH;

    // 36 unique window taps (rows hh..hh+2, cols wA..wA+3, ci 0..2), dup-lane u64.
    unsigned long long U[3][3][4];
    {
        const float* xb = x + (size_t)bb * (3 * 65536) + hh * 256 + wA;
#pragma unroll
        for (int ci = 0; ci < 3; ci++)
#pragma unroll
            for (int kh = 0; kh < 3; kh++) {
                const float2 v01 = *(const float2*)(xb + ci * 65536 + kh * 256);
                const float2 v23 = *(const float2*)(xb + ci * 65536 + kh * 256 + 2);
                U[ci][kh][0] = pack2(v01.x, v01.x);
                U[ci][kh][1] = pack2(v01.y, v01.y);
                U[ci][kh][2] = pack2(v23.x, v23.x);
                U[ci][kh][3] = pack2(v23.y, v23.y);
            }
    }

    float* obA = out + (size_t)bb * (NCH * PLANE) + hh * OW + wA;   // B = obA+1

    unsigned long long gateA = ~0ull, gateB = ~0ull;
    int base = 0;

    // ============ levels 0..2 (n=8,16,32; A @ cols 0-31, B @ cols 32-63) =====
#pragma unroll
    for (int lvl = 0; lvl < 3; lvl++) {
        const int n = 8 << lvl;
        const int k = 2 << lvl;
        const int G = n >> 3;

        unsigned long long ugate = ~0ull;
        if (lvl > 0) {
            const unsigned long long gab = gateA | gateB;
            unsigned lo = (unsigned)gab, hi = (unsigned)(gab >> 32);
#pragma unroll
            for (int o = 16; o; o >>= 1) {
                lo |= __shfl_xor_sync(0xffffffffu, lo, o);
                hi |= __shfl_xor_sync(0xffffffffu, hi, o);
            }
            ugate = ((unsigned long long)hi << 32) | lo;
        }

        unsigned gmag[2][4];
#pragma unroll
        for (int g = 0; g < 4; g++) { gmag[0][g] = 0u; gmag[1][g] = 0u; }

        // ---- conv + encode + zero-prefill + group-max build ----
#pragma unroll
        for (int g = 0; g < G; g++) {
            const int ib = g << 3;
            if (((ugate >> ib) & 0xFFull) == 0ull) {
#pragma unroll
                for (int j = 0; j < 8; j++) {
                    sEnc[(ib + j) * BT + t] = 0u;
                    sEnc[(32 + ib + j) * BT + t] = 0u;
                    *(float2*)(obA + (size_t)(base + ib + j) * PLANE) =
                        make_float2(0.f, 0.f);
                }
                continue;
            }
            unsigned gmA = 0u, gmB = 0u;
#pragma unroll
            for (int j2 = 0; j2 < 4; j2++) {
                const int i0 = ib + j2 * 2;
                const int pr = (base + i0) >> 1;
                const ulonglong2* wvp = (const ulonglong2*)(wshE + pr * 56);

                // FROZEN Eigen chain; one weight load feeds A and B.
                unsigned long long accA = 0ull, accB = 0ull;
#pragma unroll
                for (int z = 0; z < 13; z++) {
                    const int e0 = 2 * z, e1 = 2 * z + 1;
                    const int kh0 = e0 / 9, kw0 = (e0 % 9) / 3, ci0 = e0 % 3;
                    const int kh1 = e1 / 9, kw1 = (e1 % 9) / 3, ci1 = e1 % 3;
                    const ulonglong2 wv = wvp[z];
                    accA = ffma2(U[ci0][kh0][kw0], wv.x, accA);
                    accA = ffma2(U[ci1][kh1][kw1], wv.y, accA);
                    accB = ffma2(U[ci0][kh0][kw0 + 1], wv.x, accB);
                    accB = ffma2(U[ci1][kh1][kw1 + 1], wv.y, accB);
                }
                const ulonglong2 wl = wvp[13];          // ei=26 (kh2,kw2,ci2) + biases
                accA = ffma2(U[2][2][2], wl.x, accA);
                accB = ffma2(U[2][2][3], wl.x, accB);
                float bias0, bias1;
                unpack2(wl.y, bias0, bias1);
                float aA0, aA1, aB0, aB1;
                unpack2(accA, aA0, aA1);
                unpack2(accB, aB0, aB1);
                const float actA0 = aA0 + bias0, actA1 = aA1 + bias1;
                const float actB0 = aB0 + bias0, actB1 = aB1 + bias1;

                unsigned kA0 = __funnelshift_l(__float_as_uint(actA0),
                                               __float_as_uint(actA0), 1);
                unsigned kA1 = __funnelshift_l(__float_as_uint(actA1),
                                               __float_as_uint(actA1), 1);
                unsigned kB0 = __funnelshift_l(__float_as_uint(actB0),
                                               __float_as_uint(actB0), 1);
                unsigned kB1 = __funnelshift_l(__float_as_uint(actB1),
                                               __float_as_uint(actB1), 1);
                kA0 = ((unsigned)(gateA >> (i0    )) & 1u) ? kA0 : 0u;
                kA1 = ((unsigned)(gateA >> (i0 + 1)) & 1u) ? kA1 : 0u;
                kB0 = ((unsigned)(gateB >> (i0    )) & 1u) ? kB0 : 0u;
                kB1 = ((unsigned)(gateB >> (i0 + 1)) & 1u) ? kB1 : 0u;
                sEnc[(i0    ) * BT + t] = kA0;
                sEnc[(i0 + 1) * BT + t] = kA1;
                sEnc[(32 + i0    ) * BT + t] = kB0;
                sEnc[(32 + i0 + 1) * BT + t] = kB1;
                *(float2*)(obA + (size_t)(base + i0    ) * PLANE) = make_float2(0.f, 0.f);
                *(float2*)(obA + (size_t)(base + i0 + 1) * PLANE) = make_float2(0.f, 0.f);
                const unsigned umA0 = kA0 >> 1, umA1 = kA1 >> 1;
                const unsigned umB0 = kB0 >> 1, umB1 = kB1 >> 1;
                if (umA0 > gmA) gmA = umA0;      // ascending: first-wins kept
                if (umA1 > gmA) gmA = umA1;
                if (umB0 > gmB) gmB = umB0;
                if (umB1 > gmB) gmB = umB1;
            }
            gmag[0][g] = gmA;
            gmag[1][g] = gmB;
        }

        // ---- k extractions, A/B interleaved ----
        unsigned selA = 0u, selB = 0u;
#pragma unroll 1
        for (int s = 0; s < k; s++) {
            unsigned bmA = 0u, bmB = 0u;
            int bgA = 0, bgB = 0;
#pragma unroll
            for (int g = 0; g < 4; g++) {
                if (g < G) {
                    if (gmag[0][g] > bmA) { bmA = gmag[0][g]; bgA = g; }
                    if (gmag[1][g] > bmB) { bmB = gmag[1][g]; bgB = g; }
                }
            }
            if (!(bmA | bmB)) break;

            const int gbA = bgA << 3, gbB = bgB << 3;
            unsigned uA[8], uB[8];
#pragma unroll
            for (int j = 0; j < 8; j++) uA[j] = sEnc[(gbA + j) * BT + t];
#pragma unroll
            for (int j = 0; j < 8; j++) uB[j] = sEnc[(32 + gbB + j) * BT + t];

            if (bmA) {
                unsigned m2 = 0u, ufull = 0u, found = 0u;
                int leaf = 0;
#pragma unroll
                for (int j = 0; j < 8; j++) {
                    const unsigned um = uA[j] >> 1;
                    if (um == bmA && !found) { found = 1u; leaf = j; ufull = uA[j]; }
                    else if (um > m2) m2 = um;
                }
                const int mi = gbA + leaf;
                obA[(size_t)(base + mi) * PLANE] =
                    __uint_as_float(__funnelshift_r(ufull, ufull, 1));
                sEnc[mi * BT + t] = 0u;
#pragma unroll
                for (int g = 0; g < 4; g++)
                    if (g == bgA) gmag[0][g] = m2;
                selA |= 1u << mi;
            }
            if (bmB) {
                unsigned m2 = 0u, ufull = 0u, found = 0u;
                int leaf = 0;
#pragma unroll
                for (int j = 0; j < 8; j++) {
                    const unsigned um = uB[j] >> 1;
                    if (um == bmB && !found) { found = 1u; leaf = j; ufull = uB[j]; }
                    else if (um > m2) m2 = um;
                }
                const int mi = gbB + leaf;
                obA[(size_t)(base + mi) * PLANE + 1] =
                    __uint_as_float(__funnelshift_r(ufull, ufull, 1));
                sEnc[(32 + mi) * BT + t] = 0u;
#pragma unroll
                for (int g = 0; g < 4; g++)
                    if (g == bgB) gmag[1][g] = m2;
                selB |= 1u << mi;
            }
        }

        gateA = gate_from_sel(selA, n);
        gateB = gate_from_sel(selB, n);
        base += n;
    }

    // ============ level 3 (n=64, k=16): popc-compacted slots, <=32 live/px ====
    {
        unsigned long long ugate;
        {
            const unsigned long long gab = gateA | gateB;
            unsigned lo = (unsigned)gab, hi = (unsigned)(gab >> 32);
#pragma unroll
            for (int o = 16; o; o >>= 1) {
                lo |= __shfl_xor_sync(0xffffffffu, lo, o);
                hi |= __shfl_xor_sync(0xffffffffu, hi, o);
            }
            ugate = ((unsigned long long)hi << 32) | lo;
        }

        const int LA = __popcll(gateA);      // live counts (<=32)
        const int LB = __popcll(gateB);

        unsigned gmag[2][4];
#pragma unroll
        for (int g = 0; g < 4; g++) { gmag[0][g] = 0u; gmag[1][g] = 0u; }

#pragma unroll
        for (int g = 0; g < 8; g++) {
            const int ib = g << 3;
            if (((ugate >> ib) & 0xFFull) == 0ull) {
#pragma unroll
                for (int j = 0; j < 8; j++)
                    *(float2*)(obA + (size_t)(base + ib + j) * PLANE) =
                        make_float2(0.f, 0.f);
                continue;
            }
#pragma unroll
            for (int j2 = 0; j2 < 4; j2++) {
                const int i0 = ib + j2 * 2;
                const int pr = (base + i0) >> 1;
                const ulonglong2* wvp = (const ulonglong2*)(wshE + pr * 56);

                unsigned long long accA = 0ull, accB = 0ull;
#pragma unroll
                for (int z = 0; z < 13; z++) {
                    const int e0 = 2 * z, e1 = 2 * z + 1;
                    const int kh0 = e0 / 9, kw0 = (e0 % 9) / 3, ci0 = e0 % 3;
                    const int kh1 = e1 / 9, kw1 = (e1 % 9) / 3, ci1 = e1 % 3;
                    const ulonglong2 wv = wvp[z];
                    accA = ffma2(U[ci0][kh0][kw0], wv.x, accA);
                    accA = ffma2(U[ci1][kh1][kw1], wv.y, accA);
                    accB = ffma2(U[ci0][kh0][kw0 + 1], wv.x, accB);
                    accB = ffma2(U[ci1][kh1][kw1 + 1], wv.y, accB);
                }
                const ulonglong2 wl = wvp[13];
                accA = ffma2(U[2][2][2], wl.x, accA);
                accB = ffma2(U[2][2][3], wl.x, accB);
                float bias0, bias1;
                unpack2(wl.y, bias0, bias1);
                float aA0, aA1, aB0, aB1;
                unpack2(accA, aA0, aA1);
                unpack2(accB, aB0, aB1);
                const float actA0 = aA0 + bias0, actA1 = aA1 + bias1;
                const float actB0 = aB0 + bias0, actB1 = aB1 + bias1;

                const unsigned kA0 = __funnelshift_l(__float_as_uint(actA0),
                                                     __float_as_uint(actA0), 1);
                const unsigned kA1 = __funnelshift_l(__float_as_uint(actA1),
                                                     __float_as_uint(actA1), 1);
                const unsigned kB0 = __funnelshift_l(__float_as_uint(actB0),
                                                     __float_as_uint(actB0), 1);
                const unsigned kB1 = __funnelshift_l(__float_as_uint(actB1),
                                                     __float_as_uint(actB1), 1);
                *(float2*)(obA + (size_t)(base + i0    ) * PLANE) = make_float2(0.f, 0.f);
                *(float2*)(obA + (size_t)(base + i0 + 1) * PLANE) = make_float2(0.f, 0.f);

                // Branch-free popc compaction (ascending channel order ->
                // slot order preserves lower-index-wins).
#pragma unroll
                for (int e = 0; e < 2; e++) {
                    const int i = i0 + e;
                    const unsigned key = e ? kA1 : kA0;
                    if ((gateA >> i) & 1ull) {
                        const int slot = __popcll(gateA & ((1ull << i) - 1ull));
                        sEnc[slot * BT + t] = key;
                        const unsigned um = key >> 1;
                        const int sg = slot >> 3;
#pragma unroll
                        for (int gg = 0; gg < 4; gg++)
                            if (gg == sg && um > gmag[0][gg]) gmag[0][gg] = um;
                    }
                }
#pragma unroll
                for (int e = 0; e < 2; e++) {
                    const int i = i0 + e;
                    const unsigned key = e ? kB1 : kB0;
                    if ((gateB >> i) & 1ull) {
                        const int slot = __popcll(gateB & ((1ull << i) - 1ull));
                        sEnc[(32 + slot) * BT + t] = key;
                        const unsigned um = key >> 1;
                        const int sg = slot >> 3;
#pragma unroll
                        for (int gg = 0; gg < 4; gg++)
                            if (gg == sg && um > gmag[1][gg]) gmag[1][gg] = um;
                    }
                }
            }
        }

        // ---- 16 extractions, A/B interleaved, stale slots masked ----
#pragma unroll 1
        for (int s = 0; s < 16; s++) {
            unsigned bmA = 0u, bmB = 0u;
            int bgA = 0, bgB = 0;
#pragma unroll
            for (int g = 0; g < 4; g++) {
                if (gmag[0][g] > bmA) { bmA = gmag[0][g]; bgA = g; }
                if (gmag[1][g] > bmB) { bmB = gmag[1][g]; bgB = g; }
            }
            if (!(bmA | bmB)) break;

            const int gbA = bgA << 3, gbB = bgB << 3;
            unsigned uA[8], uB[8];
#pragma unroll
            for (int j = 0; j < 8; j++) uA[j] = sEnc[(gbA + j) * BT + t];
#pragma unroll
            for (int j = 0; j < 8; j++) uB[j] = sEnc[(32 + gbB + j) * BT + t];

            if (bmA) {
                unsigned m2 = 0u, ufull = 0u, found = 0u;
                int leaf = 0;
#pragma unroll
                for (int j = 0; j < 8; j++) {
                    const unsigned um = ((gbA + j) < LA) ? (uA[j] >> 1) : 0u;
                    if (um == bmA && !found) { found = 1u; leaf = j; ufull = uA[j]; }
                    else if (um > m2) m2 = um;
                }
                const int mi = gbA + leaf;
                const int ch = nth_set_bit(gateA, mi);
                obA[(size_t)(base + ch) * PLANE] =
                    __uint_as_float(__funnelshift_r(ufull, ufull, 1));
                sEnc[mi * BT + t] = 0u;
#pragma unroll
                for (int g = 0; g < 4; g++)
                    if (g == bgA) gmag[0][g] = m2;
            }
            if (bmB) {
                unsigned m2 = 0u, ufull = 0u, found = 0u;
                int leaf = 0;
#pragma unroll
                for (int j = 0; j < 8; j++) {
                    const unsigned um = ((gbB + j) < LB) ? (uB[j] >> 1) : 0u;
                    if (um == bmB && !found) { found = 1u; leaf = j; ufull = uB[j]; }
                    else if (um > m2) m2 = um;
                }
                const int mi = gbB + leaf;
                const int ch = nth_set_bit(gateB, mi);
                obA[(size_t)(base + ch) * PLANE + 1] =
                    __uint_as_float(__funnelshift_r(ufull, ufull, 1));
                sEnc[(32 + mi) * BT + t] = 0u;
#pragma unroll
                for (int g = 0; g < 4; g++)
                    if (g == bgB) gmag[1][g] = m2;
            }
        }
    }
}

extern "C" void kernel_launch(void* const* d_in, const int* in_sizes, int n_in,
                              void* d_out, int out_size)
{
    const float* x = (const float*)d_in[0];
    const float* w = (const float*)d_in[1];
    const float* b = (const float*)d_in[2];
    float* out = (float*)d_out;

    const int grid = (NPAIRS_PIX + BT - 1) / BT;
    hrtk_kernel<<<grid, BT>>>(x, w, b, out);
}

// round 14
// speedup vs baseline: 1.2277x; 1.2277x over previous
#include <cuda_runtime.h>
#include <stdint.h>

// HierarchicalRingTopK: 3x3x3 VALID conv (120 ch) + 4-level gated top-k keep.
// x: (8,3,256,256) f32, w: (120,3,3,3) f32, b: (120,) f32 -> out: (8,120,254,254) f32
//
// FROZEN NUMERICS (rel_err == 0.0 since R4): per-channel serial fp32 FMA chain
// over the 27 taps in NHWC patch order (kh, kw, c innermost) from 0, bias
// added as a separate fp32 add. Keys rotl(bits,1). Top-k: magnitude strict->
// scan, lower index wins ties. f32x2 lanes are independent rn-FMAs.
//
// R13 = R11 (BT=160, dynamic sEnc, 20 warps/SM) plus:
//  - pair-granular warp-uniform dead-channel skip inside live groups
//    (gating bounds live channels; warp-adjacent pixels correlate).
//  - level-0 (n=8,k=2) selection fully in registers: no sEnc for level 0.

#define BT 160
#define OH 254
#define OW 254
#define PLANE (OH * OW)          // 64516
#define NPIX (8 * PLANE)         // 516128
#define NCH 120
#define NPAIR (NCH / 2)          // 60
#define ENC_BYTES (64 * BT * 4)  // 40960 (dynamic smem)

__device__ __forceinline__ unsigned long long ffma2(unsigned long long a,
                                                    unsigned long long bb_,
                                                    unsigned long long c) {
    unsigned long long d;
    asm("fma.rn.f32x2 %0, %1, %2, %3;" : "=l"(d) : "l"(a), "l"(bb_), "l"(c));
    return d;
}
__device__ __forceinline__ unsigned long long pack2(float lo, float hi) {
    unsigned long long r;
    asm("mov.b64 %0, {%1, %2};" : "=l"(r) : "f"(lo), "f"(hi));
    return r;
}
__device__ __forceinline__ void unpack2(unsigned long long v, float& lo, float& hi) {
    asm("mov.b64 {%0, %1}, %2;" : "=f"(lo), "=f"(hi) : "l"(v));
}

// Gating: selected j -> enable bits 2j..2j+3 (mod 2n). Branch-free bit-spread.
// Validated rel_err==0.0 in R8-R12. Handles the j==31 wrap for n=32.
__device__ __forceinline__ unsigned long long gate_from_sel(unsigned m, int n) {
    unsigned long long xv = m;
    xv = (xv | (xv << 16)) & 0x0000FFFF0000FFFFull;
    xv = (xv | (xv << 8 )) & 0x00FF00FF00FF00FFull;
    xv = (xv | (xv << 4 )) & 0x0F0F0F0F0F0F0F0Full;
    xv = (xv | (xv << 2 )) & 0x3333333333333333ull;
    xv = (xv | (xv << 1 )) & 0x5555555555555555ull;     // bit j -> bit 2j
    unsigned long long gg = xv | (xv << 1) | (xv << 2) | (xv << 3);
    if (n == 32 && (m >> 31)) gg |= 0x3ull;             // wrap of j=31
    const int Wn = n * 2;
    if (Wn < 64)
        gg = (gg | (gg >> Wn)) & ((1ull << Wn) - 1ull);
    return gg;
}

__global__ void __launch_bounds__(BT, 4)
hrtk_kernel(const float* __restrict__ x,
            const float* __restrict__ w,
            const float* __restrict__ b,
            float* __restrict__ out)
{
    // Pair-interleaved weights: wsh2[pr*56 + 2q+e] = w[2pr+e][q]; +54/+55 = biases.
    __shared__ float wsh2[NPAIR * 56];               // 13440 B (static)
    extern __shared__ unsigned sEnc[];               // 64 key columns x BT (dynamic)

    const int t = threadIdx.x;

    for (int q = t; q < NPAIR * 56; q += BT) {
        const int pr = q / 56;
        const int r  = q - pr * 56;
        wsh2[q] = (r < 54) ? w[(pr * 2 + (r & 1)) * 27 + (r >> 1)]
                           : b[pr * 2 + (r - 54)];
    }
    __syncthreads();

    const int p = blockIdx.x * BT + t;
    if (p >= NPIX) return;
    // NPIX = 160*3225 + 128: tail block keeps warps 0-3 fully live, warp 4
    // exits whole -> full-mask shuffles safe in every surviving warp.

    const int ww = p % OW;
    const int rest = p / OW;
    const int hh = rest % OH;
    const int bb = rest / OH;

    unsigned long long win2[27];
    const float* xb = x + (size_t)bb * (3 * 65536) + hh * 256 + ww;
#pragma unroll
    for (int ci = 0; ci < 3; ci++)
#pragma unroll
        for (int kh = 0; kh < 3; kh++)
#pragma unroll
            for (int kw = 0; kw < 3; kw++) {
                const float v = __ldg(xb + ci * 65536 + kh * 256 + kw);
                win2[ci * 9 + kh * 3 + kw] = pack2(v, v);
            }

    float* ob = out + (size_t)bb * (NCH * PLANE) + hh * OW + ww;

    unsigned long long gate;

    // ===================== level 0 (n=8, k=2): registers only ================
    {
        unsigned kk[8];
#pragma unroll
        for (int j2 = 0; j2 < 4; j2++) {
            const int i0 = j2 * 2;
            const float4* wv = (const float4*)(wsh2 + j2 * 56);
            float wrp[56];
#pragma unroll
            for (int z = 0; z < 14; z++) *(float4*)&wrp[4 * z] = wv[z];

            // FROZEN: Eigen/NHWC tap order, per-lane serial fp32 chain.
            unsigned long long acc = 0ull;
#pragma unroll
            for (int kh = 0; kh < 3; kh++)
#pragma unroll
                for (int kw = 0; kw < 3; kw++)
#pragma unroll
                    for (int ci = 0; ci < 3; ci++) {
                        const int q = ci * 9 + kh * 3 + kw;
                        acc = ffma2(win2[q],
                                    *(const unsigned long long*)&wrp[2 * q],
                                    acc);
                    }
            float a0, a1;
            unpack2(acc, a0, a1);
            const float act0 = a0 + wrp[54];
            const float act1 = a1 + wrp[55];
            const unsigned b0 = __float_as_uint(act0);
            const unsigned b1 = __float_as_uint(act1);
            kk[i0]     = __funnelshift_l(b0, b0, 1);
            kk[i0 + 1] = __funnelshift_l(b1, b1, 1);
            ob[(i0    ) * PLANE] = 0.0f;
            ob[(i0 + 1) * PLANE] = 0.0f;
        }

        // top-2 in registers: (mag<<3)|(7-i) -> max == lower-index-wins on ties
        unsigned selmask = 0u;
        unsigned long long m1 = 0ull;
#pragma unroll
        for (int i = 0; i < 8; i++) {
            const unsigned long long vi =
                ((unsigned long long)(kk[i] >> 1) << 3) | (unsigned)(7 - i);
            if (vi > m1) m1 = vi;
        }
        if (m1 >> 3) {                               // top magnitude nonzero
            const int mi1 = 7 - (int)(m1 & 7ull);
            unsigned kf1 = 0u;
#pragma unroll
            for (int i = 0; i < 8; i++) if (i == mi1) kf1 = kk[i];
            ob[mi1 * PLANE] = __uint_as_float(__funnelshift_r(kf1, kf1, 1));
            selmask |= 1u << mi1;

            unsigned long long m2 = 0ull;
#pragma unroll
            for (int i = 0; i < 8; i++) {
                unsigned long long vi =
                    ((unsigned long long)(kk[i] >> 1) << 3) | (unsigned)(7 - i);
                if (i == mi1) vi = 0ull;
                if (vi > m2) m2 = vi;
            }
            if (m2 >> 3) {
                const int mi2 = 7 - (int)(m2 & 7ull);
                unsigned kf2 = 0u;
#pragma unroll
                for (int i = 0; i < 8; i++) if (i == mi2) kf2 = kk[i];
                ob[mi2 * PLANE] = __uint_as_float(__funnelshift_r(kf2, kf2, 1));
                selmask |= 1u << mi2;
            }
        }
        gate = gate_from_sel(selmask, 8);
    }

    int base = 8;

    // ===================== levels 1..3 (n = 16,32,64) ========================
#pragma unroll
    for (int lvl = 1; lvl < 4; lvl++) {
        const int n = 8 << lvl;   // 16,32,64
        const int k = 2 << lvl;   // 4,8,16
        const int G = n >> 3;     // groups of 8 channels

        // Warp-union of gates (uniform liveness for skips).
        unsigned long long ugate;
        {
            unsigned lo = (unsigned)gate, hi = (unsigned)(gate >> 32);
#pragma unroll
            for (int o = 16; o; o >>= 1) {
                lo |= __shfl_xor_sync(0xffffffffu, lo, o);
                hi |= __shfl_xor_sync(0xffffffffu, hi, o);
            }
            ugate = ((unsigned long long)hi << 32) | lo;
        }

        unsigned gmag[8];
#pragma unroll
        for (int g = 0; g < 8; g++) gmag[g] = 0u;

        // ---- conv + encode + zero-prefill + group-max build ----
#pragma unroll
        for (int g = 0; g < G; g++) {
            const int ib = g << 3;
            unsigned gm = 0u;
            if (((ugate >> ib) & 0xFFull) == 0ull) {
#pragma unroll
                for (int j = 0; j < 8; j++) {
                    sEnc[(ib + j) * BT + t] = 0u;
                    ob[(base + ib + j) * PLANE] = 0.0f;
                }
            } else {
#pragma unroll
                for (int j2 = 0; j2 < 4; j2++) {            // 4 channel-pairs
                    const int i0 = ib + j2 * 2;
                    // pair-granular warp-uniform dead skip
                    if (((ugate >> i0) & 0x3ull) == 0ull) {
                        sEnc[(i0    ) * BT + t] = 0u;
                        sEnc[(i0 + 1) * BT + t] = 0u;
                        ob[(base + i0    ) * PLANE] = 0.0f;
                        ob[(base + i0 + 1) * PLANE] = 0.0f;
                        continue;
                    }
                    const int pr = (base + i0) >> 1;
                    const float4* wv = (const float4*)(wsh2 + pr * 56);
                    float wrp[56];
#pragma unroll
                    for (int z = 0; z < 14; z++) *(float4*)&wrp[4 * z] = wv[z];

                    // FROZEN: Eigen/NHWC tap order, per-lane serial fp32 chain.
                    unsigned long long acc = 0ull;
#pragma unroll
                    for (int kh = 0; kh < 3; kh++)
#pragma unroll
                        for (int kw = 0; kw < 3; kw++)
#pragma unroll
                            for (int ci = 0; ci < 3; ci++) {
                                const int q = ci * 9 + kh * 3 + kw;
                                acc = ffma2(win2[q],
                                            *(const unsigned long long*)&wrp[2 * q],
                                            acc);
                            }
                    float a0, a1;
                    unpack2(acc, a0, a1);
                    const float act0 = a0 + wrp[54];
                    const float act1 = a1 + wrp[55];

                    const unsigned b0 = __float_as_uint(act0);
                    const unsigned b1 = __float_as_uint(act1);
                    unsigned k0 = __funnelshift_l(b0, b0, 1);
                    unsigned k1 = __funnelshift_l(b1, b1, 1);
                    k0 = ((unsigned)(gate >> (i0    )) & 1u) ? k0 : 0u;
                    k1 = ((unsigned)(gate >> (i0 + 1)) & 1u) ? k1 : 0u;
                    sEnc[(i0    ) * BT + t] = k0;
                    sEnc[(i0 + 1) * BT + t] = k1;
                    ob[(base + i0    ) * PLANE] = 0.0f;
                    ob[(base + i0 + 1) * PLANE] = 0.0f;
                    const unsigned um0 = k0 >> 1, um1 = k1 >> 1;
                    if (um0 > gm) gm = um0;                  // ascending order:
                    if (um1 > gm) gm = um1;                  // first-wins kept
                }
            }
            gmag[g] = gm;
        }

        // ---- k extractions: register group-max scan + one 8-slot rescan ----
        unsigned selmask = 0u;
#pragma unroll 1
        for (int s = 0; s < k; s++) {
            unsigned bm = 0u;
            int bg = 0;
#pragma unroll
            for (int g = 0; g < 8; g++)
                if (g < G && gmag[g] > bm) { bm = gmag[g]; bg = g; }  // strict >
            if (!bm) break;                       // all remaining keys are zero

            unsigned m2 = 0u, ufull = 0u, found = 0u;
            int leaf = 0;
            const int gb = bg << 3;
#pragma unroll
            for (int j = 0; j < 8; j++) {
                const unsigned u = sEnc[(gb + j) * BT + t];
                const unsigned um = u >> 1;
                if (um == bm && !found) { found = 1u; leaf = j; ufull = u; }
                else if (um > m2) m2 = um;
            }
            const int mi = gb + leaf;
            ob[(base + mi) * PLANE] =
                __uint_as_float(__funnelshift_r(ufull, ufull, 1));
            sEnc[mi * BT + t] = 0u;
#pragma unroll
            for (int g = 0; g < 8; g++)
                if (g == bg) gmag[g] = m2;
            selmask |= 1u << mi;
        }

        if (lvl < 3)
            gate = gate_from_sel(selmask, n);
        base += n;
    }
}

extern "C" void kernel_launch(void* const* d_in, const int* in_sizes, int n_in,
                              void* d_out, int out_size)
{
    const float* x = (const float*)d_in[0];
    const float* w = (const float*)d_in[1];
    const float* b = (const float*)d_in[2];
    float* out = (float*)d_out;

    static int smem_ok = 0;
    if (!smem_ok) {
        cudaFuncSetAttribute(hrtk_kernel,
                             cudaFuncAttributeMaxDynamicSharedMemorySize,
                             ENC_BYTES);
        smem_ok = 1;
    }

    const int grid = (NPIX + BT - 1) / BT;
    hrtk_kernel<<<grid, BT, ENC_BYTES>>>(x, w, b, out);
}